// round 15
// baseline (speedup 1.0000x reference)
#include <cuda_runtime.h>
#include <cuda_fp16.h>
#include <cstdint>
#include <math.h>

// Two kernels bridged with PDL (programmatic dependent launch):
//   qk_bpre: B features (fp16 hi) in m16n8k16 fragment order -> gBf (128KB, L2).
//            Each thread triggers launch_dependents after its stores.
//   qk_main: A features/a-frags prologue overlaps qk_bpre; griddepcontrol.wait
//            immediately before the first gBf read. Barrier-free mainloop:
//            per 16-col step 2 coalesced LDG.128 (b-frags) + 16 MMA + stores.
// dot = ah.bh + al.bh = a.bh (B-rounding only; rel_err ~2.8e-4, budget 1e-3).

__device__ __align__(16) __half gBf[128 * 2 * 32 * 8];   // 128 KB

__device__ __forceinline__ uint32_t smem_u32(const void* p) {
    uint32_t a;
    asm("{ .reg .u64 t; cvta.to.shared.u64 t, %1; cvt.u32.u64 %0, t; }" : "=r"(a) : "l"(p));
    return a;
}
__device__ __forceinline__ void ldm_x4(uint32_t* r, uint32_t addr) {
    asm volatile("ldmatrix.sync.aligned.m8n8.x4.shared.b16 {%0,%1,%2,%3}, [%4];"
                 : "=r"(r[0]), "=r"(r[1]), "=r"(r[2]), "=r"(r[3]) : "r"(addr));
}
__device__ __forceinline__ void mma16816(float* d, const uint32_t* a,
                                         uint32_t b0, uint32_t b1) {
    asm volatile(
        "mma.sync.aligned.m16n8k16.row.col.f32.f16.f16.f32 "
        "{%0,%1,%2,%3}, {%4,%5,%6,%7}, {%8,%9}, {%0,%1,%2,%3};"
        : "+f"(d[0]), "+f"(d[1]), "+f"(d[2]), "+f"(d[3])
        : "r"(a[0]), "r"(a[1]), "r"(a[2]), "r"(a[3]), "r"(b0), "r"(b1));
}

// ---------------- Kernel 1: B-fragment precompute ----------------
__global__ void qk_bpre(const float* __restrict__ c, int C) {
    int idx = blockIdx.x * blockDim.x + threadIdx.x;
    if (idx < 2 * C) {
        int col = idx & (C - 1);       // C = 2048 (power of two)
        int g   = idx >> 11;

        float4 cv4 = *(const float4*)(c + (size_t)col * 8 + g * 4);
        float cw[4], sw[4];
        sincosf(0.5f * cv4.x, &sw[0], &cw[0]);
        sincosf(0.5f * cv4.y, &sw[1], &cw[1]);
        sincosf(0.5f * cv4.z, &sw[2], &cw[2]);
        sincosf(0.5f * cv4.w, &sw[3], &cw[3]);
        float pa[4] = {cw[0]*cw[1], cw[0]*sw[1], sw[0]*cw[1], sw[0]*sw[1]};
        float pb[4] = {cw[2]*cw[3], cw[2]*sw[3], sw[2]*cw[3], sw[2]*sw[3]};

        int ct = col >> 4, w = col & 15;
        int nt = w >> 3, nrow = w & 7;
        __half* base = gBf + ((size_t)(ct * 2 + g) * 32) * 8;

        #pragma unroll
        for (int a = 0; a < 4; a++)
            #pragma unroll
            for (int b = 0; b < 4; b++) {
                int k = a * 4 + b;                       // feature index 0..15
                __half hv = __float2half_rn(pa[a] * pb[b]);
                int L = nrow * 4 + ((k & 7) >> 1);       // lane
                int r = nt * 2 + (k >> 3);               // reg 0..3
                base[L * 8 + r * 2 + (k & 1)] = hv;
            }
    }
    // Release dependent grid (stores above are visible to waiters).
    asm volatile("griddepcontrol.launch_dependents;");
}

// ---------------- Kernel 2: main, barrier-free mainloop ----------------
// CTA: 128 rows x 512 cols. 8 warps: 4 row groups (32r) x 2 col groups (256c).
__global__ void __launch_bounds__(256, 2)
qk_main(const float* __restrict__ x, float* __restrict__ out, int C) {
    __shared__ __align__(16) unsigned char smA[20480];   // 2 groups x 128 x 80B
    const int tid = threadIdx.x, wid = tid >> 5, lane = tid & 31;
    const int row0 = blockIdx.y * 128, col0 = blockIdx.x * 512;
    const uint32_t sb = smem_u32(smA);

    // ---- A prologue (overlaps qk_bpre): fp16 hi|lo features, stride 80 ----
    if (tid < 128) {
        const float* src = x + (size_t)(row0 + tid) * 8;
        float cv[8], sv[8];
        #pragma unroll
        for (int j = 0; j < 8; j++) sincosf(0.5f * src[j], &sv[j], &cv[j]);
        float pf[4][4];
        #pragma unroll
        for (int p = 0; p < 4; p++) {
            pf[p][0] = cv[2*p] * cv[2*p+1];
            pf[p][1] = cv[2*p] * sv[2*p+1];
            pf[p][2] = sv[2*p] * cv[2*p+1];
            pf[p][3] = sv[2*p] * sv[2*p+1];
        }
        #pragma unroll
        for (int g = 0; g < 2; g++) {
            __align__(16) __half v[32];
            #pragma unroll
            for (int a = 0; a < 4; a++)
                #pragma unroll
                for (int b = 0; b < 4; b++) {
                    float f = pf[2*g][a] * pf[2*g+1][b];
                    __half hi = __float2half_rn(f);
                    v[a*4+b]      = hi;
                    v[16 + a*4+b] = __float2half_rn(f - __half2float(hi));
                }
            uint4* dst = (uint4*)(smA + g * 10240 + tid * 80);
            #pragma unroll
            for (int j = 0; j < 4; j++) dst[j] = ((const uint4*)v)[j];
        }
    }
    __syncthreads();    // the ONLY barrier

    const int wr = wid & 3;       // row group
    const int wc = wid >> 2;      // col group

    // Persistent a-frags: af[g][mt][hl][4], 32 regs (still pre-wait).
    uint32_t af[2][2][2][4];
    {
        const uint32_t aoff =
            (uint32_t)(wr * 32 + (lane & 15)) * 80 + (lane >> 4) * 16;
        #pragma unroll
        for (int mt = 0; mt < 2; mt++)
            #pragma unroll
            for (int hl = 0; hl < 2; hl++) {
                ldm_x4(af[0][mt][hl], sb + aoff + mt * 16 * 80 + hl * 32);
                ldm_x4(af[1][mt][hl], sb + 10240 + aoff + mt * 16 * 80 + hl * 32);
            }
    }

    // Wait for qk_bpre's gBf to be ready (released by launch_dependents).
    asm volatile("griddepcontrol.wait;" ::: "memory");

    const uint4* bf = (const uint4*)gBf;
    const int ctb = (col0 >> 4) + wc * 16;     // first 16-col step
    const int colw = (lane & 3) * 2;
    const size_t rbase = (size_t)(row0 + wr * 32 + (lane >> 2));

    uint4 cur0 = bf[(ctb * 2 + 0) * 32 + lane];
    uint4 cur1 = bf[(ctb * 2 + 1) * 32 + lane];

    #pragma unroll 4
    for (int i = 0; i < 16; i++) {
        uint4 nb0, nb1;
        if (i < 15) {
            nb0 = bf[((ctb + i + 1) * 2 + 0) * 32 + lane];
            nb1 = bf[((ctb + i + 1) * 2 + 1) * 32 + lane];
        }

        float acc[2][2][2][4] = {};   // [g][mt][nt][4]
        // k-step 1: ah . bh  (8 independent MMAs)
        #pragma unroll
        for (int mt = 0; mt < 2; mt++) {
            mma16816(acc[0][mt][0], af[0][mt][0], cur0.x, cur0.y);
            mma16816(acc[1][mt][0], af[1][mt][0], cur1.x, cur1.y);
            mma16816(acc[0][mt][1], af[0][mt][0], cur0.z, cur0.w);
            mma16816(acc[1][mt][1], af[1][mt][0], cur1.z, cur1.w);
        }
        // k-step 2: al . bh
        #pragma unroll
        for (int mt = 0; mt < 2; mt++) {
            mma16816(acc[0][mt][0], af[0][mt][1], cur0.x, cur0.y);
            mma16816(acc[1][mt][0], af[1][mt][1], cur1.x, cur1.y);
            mma16816(acc[0][mt][1], af[0][mt][1], cur0.z, cur0.w);
            mma16816(acc[1][mt][1], af[1][mt][1], cur1.z, cur1.w);
        }

        // Epilogue: out = |D1 * D2|
        const int cbase = col0 + wc * 256 + i * 16 + colw;
        #pragma unroll
        for (int mt = 0; mt < 2; mt++)
            #pragma unroll
            for (int nt = 0; nt < 2; nt++) {
                size_t rm = rbase + mt * 16;
                int cc = cbase + nt * 8;
                float2 v;
                v.x = fabsf(acc[0][mt][nt][0] * acc[1][mt][nt][0]);
                v.y = fabsf(acc[0][mt][nt][1] * acc[1][mt][nt][1]);
                *(float2*)(out + rm * C + cc) = v;
                v.x = fabsf(acc[0][mt][nt][2] * acc[1][mt][nt][2]);
                v.y = fabsf(acc[0][mt][nt][3] * acc[1][mt][nt][3]);
                *(float2*)(out + (rm + 8) * C + cc) = v;
            }

        cur0 = nb0; cur1 = nb1;
    }
}

extern "C" void kernel_launch(void* const* d_in, const int* in_sizes, int n_in,
                              void* d_out, int out_size) {
    const float* x = (const float*)d_in[0];
    const float* c = (const float*)d_in[1];
    float* out = (float*)d_out;

    int B = in_sizes[0] / 8;   // 8192
    int C = in_sizes[1] / 8;   // 2048

    qk_bpre<<<(2 * C + 255) / 256, 256>>>(c, C);

    // PDL: qk_main launches immediately; its prologue overlaps qk_bpre,
    // and it blocks at griddepcontrol.wait until gBf is published.
    cudaLaunchConfig_t cfg = {};
    cfg.gridDim = dim3(C / 512, B / 128);   // (4, 64) = 256 CTAs
    cfg.blockDim = dim3(256, 1, 1);
    cfg.dynamicSmemBytes = 0;
    cudaLaunchAttribute attr[1];
    attr[0].id = cudaLaunchAttributeProgrammaticStreamSerialization;
    attr[0].val.programmaticStreamSerializationAllowed = 1;
    cfg.attrs = attr;
    cfg.numAttrs = 1;
    cudaLaunchKernelEx(&cfg, qk_main, x, out, C);
}

// round 16
// speedup vs baseline: 1.1070x; 1.1070x over previous
#include <cuda_runtime.h>
#include <cuda_fp16.h>
#include <cstdint>
#include <math.h>

// Single fused kernel, barrier-free mainloop, single k-step MMA.
// CTA: 128 rows x 512 cols, 8 warps = 4 row groups (32r) x 2 col groups (256c).
// A and B features both fp16 (hi rounding each): dot = ah.bh,
//   rel_err ~ sqrt(2)*2.8e-4 ~ 4e-4 (budget 1e-3).
// Prologue (one barrier):
//   tid<128: A features fp16, stride 48 (conflict-free ldmatrix phases).
//   all tids: 4 (col,g) units -> B features packed in m16n8k16 B-fragment
//             order in smem (4 STS.64 per unit).
// Mainloop per warp, per 16-col step: 2 LDS.128 + 8 MMA + product + stores.

#define SM_A  0            // 2 groups x 128 rows x 48B = 12288
#define SM_B  12288        // 32 ct x 2 g x 32 lanes x 16B = 32768
#define SM_TOT 45056       // static smem (< 48KB)

__device__ __forceinline__ uint32_t smem_u32(const void* p) {
    uint32_t a;
    asm("{ .reg .u64 t; cvta.to.shared.u64 t, %1; cvt.u32.u64 %0, t; }" : "=r"(a) : "l"(p));
    return a;
}
__device__ __forceinline__ void ldm_x4(uint32_t* r, uint32_t addr) {
    asm volatile("ldmatrix.sync.aligned.m8n8.x4.shared.b16 {%0,%1,%2,%3}, [%4];"
                 : "=r"(r[0]), "=r"(r[1]), "=r"(r[2]), "=r"(r[3]) : "r"(addr));
}
__device__ __forceinline__ void mma16816(float* d, const uint32_t* a,
                                         uint32_t b0, uint32_t b1) {
    asm volatile(
        "mma.sync.aligned.m16n8k16.row.col.f32.f16.f16.f32 "
        "{%0,%1,%2,%3}, {%4,%5,%6,%7}, {%8,%9}, {%0,%1,%2,%3};"
        : "+f"(d[0]), "+f"(d[1]), "+f"(d[2]), "+f"(d[3])
        : "r"(a[0]), "r"(a[1]), "r"(a[2]), "r"(a[3]), "r"(b0), "r"(b1));
}
__device__ __forceinline__ unsigned long long pack4h(float f0, float f1,
                                                     float f2, float f3) {
    __half2 lo = __floats2half2_rn(f0, f1);
    __half2 hi = __floats2half2_rn(f2, f3);
    unsigned long long r;
    asm("mov.b64 %0, {%1, %2};" : "=l"(r)
        : "r"(*(unsigned int*)&lo), "r"(*(unsigned int*)&hi));
    return r;
}

__global__ void __launch_bounds__(256, 2)
qk_one(const float* __restrict__ x, const float* __restrict__ c,
       float* __restrict__ out, int C) {
    __shared__ __align__(16) unsigned char sm[SM_TOT];
    const int tid = threadIdx.x, wid = tid >> 5, lane = tid & 31;
    const int row0 = blockIdx.y * 128, col0 = blockIdx.x * 512;
    const uint32_t sb = smem_u32(sm);

    // ---------------- Prologue ----------------
    // A features: tids 0-127, one row each, fp16 hi only, stride 48.
    if (tid < 128) {
        const float* src = x + (size_t)(row0 + tid) * 8;
        float cv[8], sv[8];
        #pragma unroll
        for (int j = 0; j < 8; j++) sincosf(0.5f * src[j], &sv[j], &cv[j]);
        float pf[4][4];
        #pragma unroll
        for (int p = 0; p < 4; p++) {
            pf[p][0] = cv[2*p] * cv[2*p+1];
            pf[p][1] = cv[2*p] * sv[2*p+1];
            pf[p][2] = sv[2*p] * cv[2*p+1];
            pf[p][3] = sv[2*p] * sv[2*p+1];
        }
        #pragma unroll
        for (int g = 0; g < 2; g++) {
            __align__(16) __half v[16];
            #pragma unroll
            for (int a = 0; a < 4; a++)
                #pragma unroll
                for (int b = 0; b < 4; b++)
                    v[a*4+b] = __float2half_rn(pf[2*g][a] * pf[2*g+1][b]);
            uint4* dst = (uint4*)(sm + SM_A + g * 6144 + tid * 48);
            dst[0] = ((const uint4*)v)[0];
            dst[1] = ((const uint4*)v)[1];
        }
    }

    // B fragments: 1024 (col,g) units, 4 per thread, in m16n8k16 frag order.
    #pragma unroll
    for (int p = 0; p < 4; p++) {
        const int u = tid + p * 256;        // 0..1023
        const int col = u & 511, g = u >> 9;
        float4 cv4 = *(const float4*)(c + (size_t)(col0 + col) * 8 + g * 4);
        float cw[4], sw[4];
        sincosf(0.5f * cv4.x, &sw[0], &cw[0]);
        sincosf(0.5f * cv4.y, &sw[1], &cw[1]);
        sincosf(0.5f * cv4.z, &sw[2], &cw[2]);
        sincosf(0.5f * cv4.w, &sw[3], &cw[3]);
        float pa[4] = {cw[0]*cw[1], cw[0]*sw[1], sw[0]*cw[1], sw[0]*sw[1]};
        float pb[4] = {cw[2]*cw[3], cw[2]*sw[3], sw[2]*cw[3], sw[2]*sw[3]};

        const int ct = col >> 4, w = col & 15;
        const int nt = w >> 3, nrow = w & 7;
        unsigned char* base = sm + SM_B + ((ct * 2 + g) * 32) * 16 + nt * 8;
        #pragma unroll
        for (int j = 0; j < 4; j++) {
            int k0 = 2 * j, k1 = 2 * j + 1, k8 = 2 * j + 8, k9 = 2 * j + 9;
            unsigned long long v = pack4h(
                pa[k0 >> 2] * pb[k0 & 3], pa[k1 >> 2] * pb[k1 & 3],
                pa[k8 >> 2] * pb[k8 & 3], pa[k9 >> 2] * pb[k9 & 3]);
            *(unsigned long long*)(base + (nrow * 4 + j) * 16) = v;
        }
    }
    __syncthreads();    // the ONLY barrier

    // ---------------- Persistent a-frags ----------------
    const int wr = wid & 3;       // row group
    const int wc = wid >> 2;      // col group
    uint32_t af[2][2][4];         // [g][mt][4], 16 regs
    {
        const uint32_t aoff =
            (uint32_t)(wr * 32 + (lane & 15)) * 48 + (lane >> 4) * 16;
        #pragma unroll
        for (int mt = 0; mt < 2; mt++) {
            ldm_x4(af[0][mt], sb + SM_A + aoff + mt * 16 * 48);
            ldm_x4(af[1][mt], sb + SM_A + 6144 + aoff + mt * 16 * 48);
        }
    }

    const int colw = (lane & 3) * 2;
    const size_t rbase = (size_t)(row0 + wr * 32 + (lane >> 2));
    const uint32_t bbase = sb + SM_B + lane * 16;

    #pragma unroll 4
    for (int i = 0; i < 16; i++) {
        const int ct = wc * 16 + i;           // CTA-local 16-col step
        uint4 cur0, cur1;
        {
            const uint32_t a0 = bbase + (uint32_t)(ct * 2 + 0) * 512;
            const uint32_t a1 = bbase + (uint32_t)(ct * 2 + 1) * 512;
            asm volatile("ld.shared.v4.b32 {%0,%1,%2,%3}, [%4];"
                         : "=r"(cur0.x), "=r"(cur0.y), "=r"(cur0.z), "=r"(cur0.w)
                         : "r"(a0));
            asm volatile("ld.shared.v4.b32 {%0,%1,%2,%3}, [%4];"
                         : "=r"(cur1.x), "=r"(cur1.y), "=r"(cur1.z), "=r"(cur1.w)
                         : "r"(a1));
        }

        float acc[2][2][2][4] = {};   // [g][mt][nt][4]
        // Single k-step: 8 independent MMAs.
        #pragma unroll
        for (int mt = 0; mt < 2; mt++) {
            mma16816(acc[0][mt][0], af[0][mt], cur0.x, cur0.y);
            mma16816(acc[1][mt][0], af[1][mt], cur1.x, cur1.y);
            mma16816(acc[0][mt][1], af[0][mt], cur0.z, cur0.w);
            mma16816(acc[1][mt][1], af[1][mt], cur1.z, cur1.w);
        }

        // Epilogue: out = |D1 * D2|
        const int cbase = col0 + ct * 16 + colw;
        #pragma unroll
        for (int mt = 0; mt < 2; mt++)
            #pragma unroll
            for (int nt = 0; nt < 2; nt++) {
                size_t rm = rbase + mt * 16;
                int cc = cbase + nt * 8;
                float2 v;
                v.x = fabsf(acc[0][mt][nt][0] * acc[1][mt][nt][0]);
                v.y = fabsf(acc[0][mt][nt][1] * acc[1][mt][nt][1]);
                *(float2*)(out + rm * C + cc) = v;
                v.x = fabsf(acc[0][mt][nt][2] * acc[1][mt][nt][2]);
                v.y = fabsf(acc[0][mt][nt][3] * acc[1][mt][nt][3]);
                *(float2*)(out + (rm + 8) * C + cc) = v;
            }
    }
}

extern "C" void kernel_launch(void* const* d_in, const int* in_sizes, int n_in,
                              void* d_out, int out_size) {
    const float* x = (const float*)d_in[0];
    const float* c = (const float*)d_in[1];
    float* out = (float*)d_out;

    int B = in_sizes[0] / 8;   // 8192
    int C = in_sizes[1] / 8;   // 2048

    dim3 grid(C / 512, B / 128);   // (4, 64) = 256 CTAs
    qk_one<<<grid, 256>>>(x, c, out, C);
}